// round 10
// baseline (speedup 1.0000x reference)
#include <cuda_runtime.h>
#include <cuda_bf16.h>
#include <math.h>
#include <stdint.h>

#define H 1024
#define E 64
#define MAXN 32768
#define BM 128
#define AST 144u          // padded smem row stride for B (bytes)
#define MAXSUS 8192

// gemm smem: B double-buffered (2 stages x (hi+lo)) = 36864 B.
// After the mainloop the same smem is reused as a 128x65-float logits tile (33280 B).
#define B_LO    9216u
#define B_STAGE 18432u
#define SMEM_BYTES 36864

// ---------------- scratch (no allocation allowed) ----------------
__device__ float         g_logits[(size_t)MAXN * E];   // probs (written by fused kernel)
__device__ unsigned      g_keys[(size_t)MAXN * E];     // token-major mono keys (0 = unassigned)
__device__ unsigned      g_keyT[(size_t)E * MAXN];     // expert-major keys
__device__ unsigned      g_thresh[E];
__device__ __align__(256) __nv_bfloat16 g_whi[E * H];
__device__ __align__(256) __nv_bfloat16 g_wlo[E * H];
__device__ float         g_fi[E];
__device__ float         g_pi[E];
__device__ int           g_nsus;
__device__ unsigned      g_sus[MAXSUS];

__device__ __forceinline__ unsigned mono_key(float f) {
    unsigned u = __float_as_uint(f);
    return (u & 0x80000000u) ? ~u : (u | 0x80000000u);
}

static __device__ __forceinline__ uint32_t smem_u32(const void* p) {
    uint32_t a;
    asm("{ .reg .u64 t; cvta.to.shared.u64 t, %1; cvt.u32.u64 %0, t; }" : "=r"(a) : "l"(p));
    return a;
}
static __device__ __forceinline__ void cp16(uint32_t dst, const void* src) {
    asm volatile("cp.async.ca.shared.global [%0], [%1], 16;" :: "r"(dst), "l"(src) : "memory");
}
static __device__ __forceinline__ void ldm_x4(uint32_t* r, uint32_t addr) {
    asm volatile("ldmatrix.sync.aligned.m8n8.x4.shared.b16 {%0,%1,%2,%3}, [%4];"
                 : "=r"(r[0]), "=r"(r[1]), "=r"(r[2]), "=r"(r[3]) : "r"(addr));
}
static __device__ __forceinline__ void mma16816(float* c, const uint32_t* a, const uint32_t* b) {
    asm volatile("mma.sync.aligned.m16n8k16.row.col.f32.bf16.bf16.f32 "
                 "{%0,%1,%2,%3}, {%4,%5,%6,%7}, {%8,%9}, {%0,%1,%2,%3};"
                 : "+f"(c[0]), "+f"(c[1]), "+f"(c[2]), "+f"(c[3])
                 : "r"(a[0]), "r"(a[1]), "r"(a[2]), "r"(a[3]), "r"(b[0]), "r"(b[1]));
}
static __device__ __forceinline__ void cvt_split(float a, float b, uint32_t& hi, uint32_t& lo) {
    __nv_bfloat162 h = __floats2bfloat162_rn(a, b);
    hi = *reinterpret_cast<uint32_t*>(&h);
    __nv_bfloat162 l = __floats2bfloat162_rn(a - __low2float(h), b - __high2float(h));
    lo = *reinterpret_cast<uint32_t*>(&l);
}

// ---------------- convert gate_w + init (fused) ----------------
__global__ __launch_bounds__(256) void convinit_kernel(const float* __restrict__ w) {
    int i = blockIdx.x * blockDim.x + threadIdx.x;
    if (i < E * H) {
        float v = w[i];
        __nv_bfloat16 h = __float2bfloat16(v);
        g_whi[i] = h;
        g_wlo[i] = __float2bfloat16(v - __bfloat162float(h));
    }
    if (blockIdx.x == 0 && threadIdx.x < E) {
        int t = threadIdx.x;
        g_fi[t] = 0.f; g_pi[t] = 0.f;
        if (t == 0) g_nsus = 0;
    }
}

// ---------------- fused HMMA GEMM + router ----------------
__global__ __launch_bounds__(256, 2) void gemm_router_kernel(const float* __restrict__ x,
                                                             float* __restrict__ out_top1,
                                                             int N) {
    extern __shared__ __align__(16) char smem[];
    uint32_t sb = smem_u32(smem);
    float* sm_l = (float*)smem;                 // 128 x 65 floats after mainloop
    int tid = threadIdx.x, lane = tid & 31, wid = tid >> 5;
    int n0 = blockIdx.x * BM;
    int m0 = wid * 16;

    // ---- GEMM mainloop: A fragment-direct from gmem, B double-buffered smem ----
    const float* xA  = x + (size_t)(n0 + m0 + (lane >> 2)) * H + (lane & 3) * 2;
    const float* xA8 = xA + 8 * H;
    uint32_t b_ld_off = (uint32_t)((lane & 7) + ((lane >> 4) & 1) * 8) * AST
                      + (uint32_t)((lane >> 3) & 1) * 16u;

    float acc[8][4];
#pragma unroll
    for (int i = 0; i < 8; i++)
#pragma unroll
        for (int j = 0; j < 4; j++) acc[i][j] = 0.f;

    float2 cur[16], nxt[16];
#pragma unroll
    for (int kt = 0; kt < 4; kt++) {
        int kb = kt * 16;
        cur[kt * 4 + 0] = *(const float2*)(xA  + kb);
        cur[kt * 4 + 1] = *(const float2*)(xA8 + kb);
        cur[kt * 4 + 2] = *(const float2*)(xA  + kb + 8);
        cur[kt * 4 + 3] = *(const float2*)(xA8 + kb + 8);
    }
#pragma unroll
    for (int j = 0; j < 2; j++) {
        int idx = tid * 2 + j;
        int n = idx >> 3, seg = idx & 7;
        uint32_t off = (uint32_t)n * AST + (uint32_t)seg * 16u;
        cp16(sb + off,        (const char*)g_whi + n * 2048 + seg * 16);
        cp16(sb + B_LO + off, (const char*)g_wlo + n * 2048 + seg * 16);
    }
    asm volatile("cp.async.commit_group;" ::: "memory");
    asm volatile("cp.async.wait_group 0;" ::: "memory");
    __syncthreads();

    for (int c = 0; c < 16; c++) {
        int cs = c & 1, ns = cs ^ 1;
        if (c < 15) {
            uint32_t bb = sb + (uint32_t)ns * B_STAGE;
#pragma unroll
            for (int j = 0; j < 2; j++) {
                int idx = tid * 2 + j;
                int n = idx >> 3, seg = idx & 7;
                uint32_t off = (uint32_t)n * AST + (uint32_t)seg * 16u;
                cp16(bb + off,        (const char*)g_whi + n * 2048 + (c + 1) * 128 + seg * 16);
                cp16(bb + B_LO + off, (const char*)g_wlo + n * 2048 + (c + 1) * 128 + seg * 16);
            }
            asm volatile("cp.async.commit_group;" ::: "memory");
            int cb = (c + 1) * 64;
#pragma unroll
            for (int kt = 0; kt < 4; kt++) {
                int kb = cb + kt * 16;
                nxt[kt * 4 + 0] = *(const float2*)(xA  + kb);
                nxt[kt * 4 + 1] = *(const float2*)(xA8 + kb);
                nxt[kt * 4 + 2] = *(const float2*)(xA  + kb + 8);
                nxt[kt * 4 + 3] = *(const float2*)(xA8 + kb + 8);
            }
        }
        uint32_t bbase = sb + (uint32_t)cs * B_STAGE;
#pragma unroll
        for (int kt = 0; kt < 4; kt++) {
            uint32_t ko = (uint32_t)kt * 32u;
            uint32_t ah[4], al[4];
#pragma unroll
            for (int j = 0; j < 4; j++)
                cvt_split(cur[kt * 4 + j].x, cur[kt * 4 + j].y, ah[j], al[j]);
#pragma unroll
            for (int np = 0; np < 4; np++) {
                uint32_t noff = (uint32_t)np * 16u * AST;
                uint32_t bh[4], bl[4];
                ldm_x4(bh, bbase + b_ld_off + noff + ko);
                ldm_x4(bl, bbase + B_LO + b_ld_off + noff + ko);
                mma16816(acc[2 * np],     ah, bh);
                mma16816(acc[2 * np + 1], ah, bh + 2);
                mma16816(acc[2 * np],     ah, bl);
                mma16816(acc[2 * np + 1], ah, bl + 2);
                mma16816(acc[2 * np],     al, bh);
                mma16816(acc[2 * np + 1], al, bh + 2);
            }
        }
        if (c < 15) asm volatile("cp.async.wait_group 0;" ::: "memory");
        __syncthreads();
#pragma unroll
        for (int i = 0; i < 16; i++) cur[i] = nxt[i];
    }

    // ---- stage logits into smem tile (stride 65) ----
    {
        int tokL = m0 + (lane >> 2);
        int ec = 2 * (lane & 3);
#pragma unroll
        for (int nt = 0; nt < 8; nt++) {
            sm_l[tokL * 65 + nt * 8 + ec]           = acc[nt][0];
            sm_l[tokL * 65 + nt * 8 + ec + 1]       = acc[nt][1];
            sm_l[(tokL + 8) * 65 + nt * 8 + ec]     = acc[nt][2];
            sm_l[(tokL + 8) * 65 + nt * 8 + ec + 1] = acc[nt][3];
        }
    }
    __syncthreads();

    // ---- router phase: each warp routes its 16 tokens from smem ----
    for (int q = 0; q < 16; q++) {
        int tL = m0 + q;
        int tok = n0 + tL;
        float l0 = sm_l[tL * 65 + lane];
        float l1 = sm_l[tL * 65 + lane + 32];
        float m = fmaxf(l0, l1);
#pragma unroll
        for (int o = 16; o; o >>= 1) m = fmaxf(m, __shfl_xor_sync(0xFFFFFFFFu, m, o));
        float e0 = expf(l0 - m), e1 = expf(l1 - m);
        float s = e0 + e1;
#pragma unroll
        for (int o = 16; o; o >>= 1) s += __shfl_xor_sync(0xFFFFFFFFu, s, o);
        float p0 = e0 / s, p1 = e1 / s;

        unsigned long long v0 = ((unsigned long long)(__float_as_uint(p0) | 0x80000000u) << 32)
                              | (unsigned)(63 - lane);
        unsigned long long v1 = ((unsigned long long)(__float_as_uint(p1) | 0x80000000u) << 32)
                              | (unsigned)(31 - lane);
#pragma unroll
        for (int size = 2; size <= 64; size <<= 1) {
#pragma unroll
            for (int stride = size >> 1; stride > 0; stride >>= 1) {
                if (stride == 32) {
                    unsigned long long mx = v0 > v1 ? v0 : v1;
                    unsigned long long mn = v0 > v1 ? v1 : v0;
                    v0 = mx; v1 = mn;
                } else {
                    unsigned long long q0 = __shfl_xor_sync(0xFFFFFFFFu, v0, stride);
                    unsigned long long q1 = __shfl_xor_sync(0xFFFFFFFFu, v1, stride);
                    bool low  = ((lane & stride) == 0);
                    bool asc0 = ((lane & size) != 0);
                    bool asc1 = (((lane + 32) & size) != 0);
                    v0 = ((low == asc0) ? (v0 < q0) : (v0 > q0)) ? v0 : q0;
                    v1 = ((low == asc1) ? (v1 < q1) : (v1 > q1)) ? v1 : q1;
                }
            }
        }
        float a = __uint_as_float((unsigned)(v0 >> 32) & 0x7FFFFFFFu);
        float b = __uint_as_float((unsigned)(v1 >> 32) & 0x7FFFFFFFu);
        float ia = a, ib = b;
#pragma unroll
        for (int o = 1; o < 32; o <<= 1) {
            float t = __shfl_up_sync(0xFFFFFFFFu, ia, o);
            if (lane >= o) ia += t;
            float t2 = __shfl_up_sync(0xFFFFFFFFu, ib, o);
            if (lane >= o) ib += t2;
        }
        float totalA = __shfl_sync(0xFFFFFFFFu, ia, 31);
        float S0 = ia - a;
        float S1 = totalA + ib - b;
        unsigned key0 = (S0 < 0.9f) ? mono_key(a - (float)(lane + 1))  : 0u;
        unsigned key1 = (S1 < 0.9f) ? mono_key(b - (float)(lane + 33)) : 0u;
        int idx0 = 63 - (int)(v0 & 63u);
        int idx1 = 63 - (int)(v1 & 63u);

        // scatter keys into this token's smem row (logits no longer needed)
        unsigned* sk = (unsigned*)(sm_l + tL * 65);
        sk[idx0] = key0;
        sk[idx1] = key1;
        __syncwarp();
        unsigned k0 = sk[lane], k1 = sk[lane + 32];
        g_keys[(size_t)tok * E + lane]      = k0;
        g_keys[(size_t)tok * E + lane + 32] = k1;
        g_logits[(size_t)tok * E + lane]      = p0;
        g_logits[(size_t)tok * E + lane + 32] = p1;

        int etop1 = __shfl_sync(0xFFFFFFFFu, idx0, 0);
        int etop2 = __shfl_sync(0xFFFFFFFFu, idx0, 1);
        float ptop = __shfl_sync(0xFFFFFFFFu, a, 0);
        float lt1 = __shfl_sync(0xFFFFFFFFu, a, 0);  // top logit gap via probs? use logits:
        // recover top-2 logits from smem row is overwritten; use l0/l1 shuffles instead
        float t1a = __shfl_sync(0xFFFFFFFFu, l0, etop1 & 31);
        float t1b = __shfl_sync(0xFFFFFFFFu, l1, etop1 & 31);
        float t2a = __shfl_sync(0xFFFFFFFFu, l0, etop2 & 31);
        float t2b = __shfl_sync(0xFFFFFFFFu, l1, etop2 & 31);
        lt1 = (etop1 < 32) ? t1a : t1b;
        float lt2 = (etop2 < 32) ? t2a : t2b;
        if (lane == 0) {
            out_top1[tok] = (float)etop1;
            atomicAdd(&g_fi[etop1], 1.f);
            atomicAdd(&g_pi[etop1], ptop);
            if ((lt1 - lt2) < 1e-4f) {
                int sp = atomicAdd(&g_nsus, 1);
                if (sp < MAXSUS)
                    g_sus[sp] = (unsigned)tok | ((unsigned)etop1 << 15) | ((unsigned)etop2 << 21);
            }
        }
    }
    __syncthreads();

    // ---- expert-major keyT tile: 64 experts x 128 tokens, coalesced 512B runs ----
    for (int i = tid; i < E * BM; i += 256) {
        int e = i >> 7, tl = i & 127;
        g_keyT[(size_t)e * N + n0 + tl] = ((unsigned*)(sm_l + tl * 65))[e];
    }
}

// ---------------- fp64 argmax repair: one BLOCK per suspect ----------------
__global__ __launch_bounds__(128) void repair_kernel(const float* __restrict__ x,
                                                     const float* __restrict__ w,
                                                     float* __restrict__ out_top1) {
    __shared__ double reda[4], redb[4];
    int n = g_nsus;
    if (n > MAXSUS) n = MAXSUS;
    int tid = threadIdx.x, lane = tid & 31, wrp = tid >> 5;
    for (int s = blockIdx.x; s < n; s += gridDim.x) {
        unsigned pk = g_sus[s];
        int t  = (int)(pk & 0x7FFFu);
        int ea = (int)((pk >> 15) & 63u);
        int eb = (int)((pk >> 21) & 63u);
        const float4* xr = (const float4*)(x + (size_t)t * H);
        const float4* wa = (const float4*)(w + (size_t)ea * H);
        const float4* wb = (const float4*)(w + (size_t)eb * H);
        int i0 = tid * 2;
        float4 x0 = xr[i0], x1 = xr[i0 + 1];
        float4 a0 = wa[i0], a1 = wa[i0 + 1];
        float4 b0 = wb[i0], b1 = wb[i0 + 1];
        double da = (double)x0.x * a0.x + (double)x0.y * a0.y
                  + (double)x0.z * a0.z + (double)x0.w * a0.w
                  + (double)x1.x * a1.x + (double)x1.y * a1.y
                  + (double)x1.z * a1.z + (double)x1.w * a1.w;
        double db = (double)x0.x * b0.x + (double)x0.y * b0.y
                  + (double)x0.z * b0.z + (double)x0.w * b0.w
                  + (double)x1.x * b1.x + (double)x1.y * b1.y
                  + (double)x1.z * b1.z + (double)x1.w * b1.w;
#pragma unroll
        for (int o = 16; o; o >>= 1) {
            da += __shfl_xor_sync(0xFFFFFFFFu, da, o);
            db += __shfl_xor_sync(0xFFFFFFFFu, db, o);
        }
        if (lane == 0) { reda[wrp] = da; redb[wrp] = db; }
        __syncthreads();
        if (tid == 0) {
            double A = reda[0] + reda[1] + reda[2] + reda[3];
            double B = redb[0] + redb[1] + redb[2] + redb[3];
            int win = (B > A || (B == A && eb < ea)) ? eb : ea;
            out_top1[t] = (float)win;
        }
        __syncthreads();
    }
}

// ---------------- select: single kernel, 1 block/expert, 3 radix passes internal ----------------
__global__ __launch_bounds__(256) void select_kernel(int N, int C) {
    int e = blockIdx.x, t = threadIdx.x;
    __shared__ unsigned h[2048];
    __shared__ unsigned part[256], incl[256];
    __shared__ unsigned s_prefix, s_rem;
    __shared__ int s_done;
    if (t == 0) { s_prefix = 0u; s_rem = (unsigned)C; s_done = 0; }
    const uint4* col = (const uint4*)(g_keyT + (size_t)e * N);
    int n4 = N >> 2;
    __syncthreads();

    for (int pass = 0; pass < 3; pass++) {
        if (s_done) break;   // uniform: s_done only changes before a syncthreads
        for (int i = t; i < 2048; i += 256) h[i] = 0u;
        __syncthreads();
        unsigned pref = s_prefix;
        for (int i = t; i < n4; i += 256) {
            uint4 kv = col[i];
            unsigned ks[4] = {kv.x, kv.y, kv.z, kv.w};
#pragma unroll
            for (int j = 0; j < 4; j++) {
                unsigned k = ks[j];
                if (!k) continue;
                bool mt; unsigned d;
                if (pass == 0)      { mt = true;                 d = k >> 21; }
                else if (pass == 1) { mt = ((k >> 21) == pref);  d = (k >> 10) & 0x7FFu; }
                else                { mt = ((k >> 10) == pref);  d = k & 0x3FFu; }
                if (mt) atomicAdd(&h[d], 1u);
            }
        }
        __syncthreads();
        // suffix scan over 2048 bins (8 per thread, descending)
        unsigned mybin[8];
        unsigned ssum = 0;
#pragma unroll
        for (int j = 0; j < 8; j++) { mybin[j] = h[2047 - (8 * t + j)]; ssum += mybin[j]; }
        part[t] = ssum; incl[t] = ssum;
        __syncthreads();
        for (int off = 1; off < 256; off <<= 1) {
            unsigned v = (t >= off) ? incl[t - off] : 0u;
            __syncthreads();
            incl[t] += v;
            __syncthreads();
        }
        unsigned rem = s_rem;
        if (pass == 0 && incl[255] <= rem) {
            // fewer assigned than capacity: keep all assigned
            if (t == 0) { g_thresh[e] = 1u; s_done = 1; }
            __syncthreads();
            continue;
        }
        unsigned ex = incl[t] - part[t];
        if (ex < rem && incl[t] >= rem) {
            unsigned r = rem - ex;
            int digit = 0;
#pragma unroll
            for (int j = 0; j < 8; j++) {
                unsigned cnt = mybin[j];
                if (cnt >= r) { digit = 2047 - (8 * t + j); break; }
                r -= cnt;
            }
            if (pass == 0)      s_prefix = (unsigned)digit;
            else if (pass == 1) s_prefix = (s_prefix << 11) | (unsigned)digit;
            else                g_thresh[e] = (s_prefix << 10) | (unsigned)digit;
            s_rem = r;
        }
        __syncthreads();
    }
}

// ---------------- finalize mask + scores + aux ----------------
__global__ __launch_bounds__(256) void finalize_kernel(float* __restrict__ mask_out,
                                                       float* __restrict__ scores_out,
                                                       float* __restrict__ out_aux, int N) {
    __shared__ unsigned th[64];
    int t = threadIdx.x;
    if (blockIdx.x == 0 && t < 32) {
        float v = g_fi[t] * g_pi[t] + g_fi[t + 32] * g_pi[t + 32];
#pragma unroll
        for (int o = 16; o; o >>= 1) v += __shfl_xor_sync(0xFFFFFFFFu, v, o);
        if (t == 0) out_aux[0] = (float)E * (v / ((float)N * (float)N)) * 0.01f;
    }
    if (t < 64) th[t] = g_thresh[t];
    __syncthreads();
    size_t base = (size_t)blockIdx.x * 2048 + (size_t)t * 8;
#pragma unroll
    for (int j = 0; j < 2; j++) {
        size_t o = base + (size_t)j * 4;
        uint4  k = *(const uint4*)(g_keys + o);
        float4 p = *(const float4*)(g_logits + o);
        int e0 = (int)(o & 63);
        float4 mo, so;
        bool b0 = k.x && k.x >= th[e0 + 0];
        bool b1 = k.y && k.y >= th[e0 + 1];
        bool b2 = k.z && k.z >= th[e0 + 2];
        bool b3 = k.w && k.w >= th[e0 + 3];
        mo.x = b0 ? 1.f : 0.f; so.x = b0 ? p.x : 0.f;
        mo.y = b1 ? 1.f : 0.f; so.y = b1 ? p.y : 0.f;
        mo.z = b2 ? 1.f : 0.f; so.z = b2 ? p.z : 0.f;
        mo.w = b3 ? 1.f : 0.f; so.w = b3 ? p.w : 0.f;
        *(float4*)(mask_out + o)   = mo;
        *(float4*)(scores_out + o) = so;
    }
}

// ---------------- launch ----------------
extern "C" void kernel_launch(void* const* d_in, const int* in_sizes, int n_in,
                              void* d_out, int out_size) {
    const float* x = (const float*)d_in[0];
    const float* w = (const float*)d_in[1];
    int N = in_sizes[0] / H;            // 32768
    int C = (N + E - 1) / E;            // capacity (factor 1.0)
    if (C > N) C = N;

    float* out      = (float*)d_out;
    float* mask_out = out;
    float* scr_out  = out + (size_t)N * E;
    float* aux_out  = out + (size_t)2 * N * E;
    float* top1_out = out + (size_t)2 * N * E + 1;

    cudaFuncSetAttribute(gemm_router_kernel, cudaFuncAttributeMaxDynamicSharedMemorySize, SMEM_BYTES);

    convinit_kernel<<<(E * H + 255) / 256, 256>>>(w);
    gemm_router_kernel<<<N / BM, 256, SMEM_BYTES>>>(x, top1_out, N);
    repair_kernel<<<512, 128>>>(x, w, top1_out);
    select_kernel<<<E, 256>>>(N, C);
    finalize_kernel<<<(N * E) / 2048, 256>>>(mask_out, scr_out, aux_out, N);
}

// round 11
// speedup vs baseline: 1.0336x; 1.0336x over previous
#include <cuda_runtime.h>
#include <cuda_bf16.h>
#include <math.h>
#include <stdint.h>

#define H 1024
#define E 64
#define MAXN 32768
#define BM 128
#define AST 144u          // padded smem row stride for B (bytes)
#define MAXSUS 8192
#define SEG 8

// gemm smem: B double-buffered (2 stages x (hi+lo)) = 36864 B.
// After the mainloop the same smem is reused as a 128x65-float logits tile (33280 B).
#define B_LO    9216u
#define B_STAGE 18432u
#define SMEM_BYTES 36864

// ---------------- scratch (no allocation allowed) ----------------
__device__ float         g_logits[(size_t)MAXN * E];   // probs (written by fused kernel)
__device__ unsigned      g_keys[(size_t)MAXN * E];     // token-major mono keys (0 = unassigned)
__device__ unsigned      g_keyT[(size_t)E * MAXN];     // expert-major keys
__device__ unsigned      g_hist[E][2048];
__device__ unsigned      g_prefix[E];
__device__ unsigned      g_rem[E];
__device__ unsigned      g_thresh[E];
__device__ __align__(256) __nv_bfloat16 g_whi[E * H];
__device__ __align__(256) __nv_bfloat16 g_wlo[E * H];
__device__ float         g_fi[E];
__device__ float         g_pi[E];
__device__ int           g_nsus;
__device__ unsigned      g_sus[MAXSUS];

__device__ __forceinline__ unsigned mono_key(float f) {
    unsigned u = __float_as_uint(f);
    return (u & 0x80000000u) ? ~u : (u | 0x80000000u);
}

static __device__ __forceinline__ uint32_t smem_u32(const void* p) {
    uint32_t a;
    asm("{ .reg .u64 t; cvta.to.shared.u64 t, %1; cvt.u32.u64 %0, t; }" : "=r"(a) : "l"(p));
    return a;
}
static __device__ __forceinline__ void cp16(uint32_t dst, const void* src) {
    asm volatile("cp.async.ca.shared.global [%0], [%1], 16;" :: "r"(dst), "l"(src) : "memory");
}
static __device__ __forceinline__ void ldm_x4(uint32_t* r, uint32_t addr) {
    asm volatile("ldmatrix.sync.aligned.m8n8.x4.shared.b16 {%0,%1,%2,%3}, [%4];"
                 : "=r"(r[0]), "=r"(r[1]), "=r"(r[2]), "=r"(r[3]) : "r"(addr));
}
static __device__ __forceinline__ void mma16816(float* c, const uint32_t* a, const uint32_t* b) {
    asm volatile("mma.sync.aligned.m16n8k16.row.col.f32.bf16.bf16.f32 "
                 "{%0,%1,%2,%3}, {%4,%5,%6,%7}, {%8,%9}, {%0,%1,%2,%3};"
                 : "+f"(c[0]), "+f"(c[1]), "+f"(c[2]), "+f"(c[3])
                 : "r"(a[0]), "r"(a[1]), "r"(a[2]), "r"(a[3]), "r"(b[0]), "r"(b[1]));
}
static __device__ __forceinline__ void cvt_split(float a, float b, uint32_t& hi, uint32_t& lo) {
    __nv_bfloat162 h = __floats2bfloat162_rn(a, b);
    hi = *reinterpret_cast<uint32_t*>(&h);
    __nv_bfloat162 l = __floats2bfloat162_rn(a - __low2float(h), b - __high2float(h));
    lo = *reinterpret_cast<uint32_t*>(&l);
}

// ---------------- convert gate_w + init (fused) ----------------
__global__ __launch_bounds__(256) void convinit_kernel(const float* __restrict__ w, int C) {
    int i = blockIdx.x * blockDim.x + threadIdx.x;
    if (i < E * H) {
        float v = w[i];
        __nv_bfloat16 h = __float2bfloat16(v);
        g_whi[i] = h;
        g_wlo[i] = __float2bfloat16(v - __bfloat162float(h));
    }
    if (blockIdx.x == 0 && threadIdx.x < E) {
        int t = threadIdx.x;
        g_fi[t] = 0.f; g_pi[t] = 0.f;
        g_prefix[t] = 0u; g_rem[t] = (unsigned)C;
        if (t == 0) g_nsus = 0;
    }
}

// ---------------- fused HMMA GEMM + router ----------------
__global__ __launch_bounds__(256, 2) void gemm_router_kernel(const float* __restrict__ x,
                                                             float* __restrict__ out_top1,
                                                             int N) {
    extern __shared__ __align__(16) char smem[];
    uint32_t sb = smem_u32(smem);
    float* sm_l = (float*)smem;                 // 128 x 65 floats after mainloop
    int tid = threadIdx.x, lane = tid & 31, wid = tid >> 5;
    int n0 = blockIdx.x * BM;
    int m0 = wid * 16;

    // ---- GEMM mainloop: A fragment-direct from gmem, B double-buffered smem ----
    const float* xA  = x + (size_t)(n0 + m0 + (lane >> 2)) * H + (lane & 3) * 2;
    const float* xA8 = xA + 8 * H;
    uint32_t b_ld_off = (uint32_t)((lane & 7) + ((lane >> 4) & 1) * 8) * AST
                      + (uint32_t)((lane >> 3) & 1) * 16u;

    float acc[8][4];
#pragma unroll
    for (int i = 0; i < 8; i++)
#pragma unroll
        for (int j = 0; j < 4; j++) acc[i][j] = 0.f;

    float2 cur[16], nxt[16];
#pragma unroll
    for (int kt = 0; kt < 4; kt++) {
        int kb = kt * 16;
        cur[kt * 4 + 0] = *(const float2*)(xA  + kb);
        cur[kt * 4 + 1] = *(const float2*)(xA8 + kb);
        cur[kt * 4 + 2] = *(const float2*)(xA  + kb + 8);
        cur[kt * 4 + 3] = *(const float2*)(xA8 + kb + 8);
    }
#pragma unroll
    for (int j = 0; j < 2; j++) {
        int idx = tid * 2 + j;
        int n = idx >> 3, seg = idx & 7;
        uint32_t off = (uint32_t)n * AST + (uint32_t)seg * 16u;
        cp16(sb + off,        (const char*)g_whi + n * 2048 + seg * 16);
        cp16(sb + B_LO + off, (const char*)g_wlo + n * 2048 + seg * 16);
    }
    asm volatile("cp.async.commit_group;" ::: "memory");
    asm volatile("cp.async.wait_group 0;" ::: "memory");
    __syncthreads();

    for (int c = 0; c < 16; c++) {
        int cs = c & 1, ns = cs ^ 1;
        if (c < 15) {
            uint32_t bb = sb + (uint32_t)ns * B_STAGE;
#pragma unroll
            for (int j = 0; j < 2; j++) {
                int idx = tid * 2 + j;
                int n = idx >> 3, seg = idx & 7;
                uint32_t off = (uint32_t)n * AST + (uint32_t)seg * 16u;
                cp16(bb + off,        (const char*)g_whi + n * 2048 + (c + 1) * 128 + seg * 16);
                cp16(bb + B_LO + off, (const char*)g_wlo + n * 2048 + (c + 1) * 128 + seg * 16);
            }
            asm volatile("cp.async.commit_group;" ::: "memory");
            int cb = (c + 1) * 64;
#pragma unroll
            for (int kt = 0; kt < 4; kt++) {
                int kb = cb + kt * 16;
                nxt[kt * 4 + 0] = *(const float2*)(xA  + kb);
                nxt[kt * 4 + 1] = *(const float2*)(xA8 + kb);
                nxt[kt * 4 + 2] = *(const float2*)(xA  + kb + 8);
                nxt[kt * 4 + 3] = *(const float2*)(xA8 + kb + 8);
            }
        }
        uint32_t bbase = sb + (uint32_t)cs * B_STAGE;
#pragma unroll
        for (int kt = 0; kt < 4; kt++) {
            uint32_t ko = (uint32_t)kt * 32u;
            uint32_t ah[4], al[4];
#pragma unroll
            for (int j = 0; j < 4; j++)
                cvt_split(cur[kt * 4 + j].x, cur[kt * 4 + j].y, ah[j], al[j]);
#pragma unroll
            for (int np = 0; np < 4; np++) {
                uint32_t noff = (uint32_t)np * 16u * AST;
                uint32_t bh[4], bl[4];
                ldm_x4(bh, bbase + b_ld_off + noff + ko);
                ldm_x4(bl, bbase + B_LO + b_ld_off + noff + ko);
                mma16816(acc[2 * np],     ah, bh);
                mma16816(acc[2 * np + 1], ah, bh + 2);
                mma16816(acc[2 * np],     ah, bl);
                mma16816(acc[2 * np + 1], ah, bl + 2);
                mma16816(acc[2 * np],     al, bh);
                mma16816(acc[2 * np + 1], al, bh + 2);
            }
        }
        if (c < 15) asm volatile("cp.async.wait_group 0;" ::: "memory");
        __syncthreads();
#pragma unroll
        for (int i = 0; i < 16; i++) cur[i] = nxt[i];
    }

    // ---- stage logits into smem tile (stride 65) ----
    {
        int tokL = m0 + (lane >> 2);
        int ec = 2 * (lane & 3);
#pragma unroll
        for (int nt = 0; nt < 8; nt++) {
            sm_l[tokL * 65 + nt * 8 + ec]           = acc[nt][0];
            sm_l[tokL * 65 + nt * 8 + ec + 1]       = acc[nt][1];
            sm_l[(tokL + 8) * 65 + nt * 8 + ec]     = acc[nt][2];
            sm_l[(tokL + 8) * 65 + nt * 8 + ec + 1] = acc[nt][3];
        }
    }
    __syncthreads();

    // ---- router phase: each warp routes its 16 tokens from smem ----
    for (int q = 0; q < 16; q++) {
        int tL = m0 + q;
        int tok = n0 + tL;
        float l0 = sm_l[tL * 65 + lane];
        float l1 = sm_l[tL * 65 + lane + 32];
        float m = fmaxf(l0, l1);
#pragma unroll
        for (int o = 16; o; o >>= 1) m = fmaxf(m, __shfl_xor_sync(0xFFFFFFFFu, m, o));
        float e0 = expf(l0 - m), e1 = expf(l1 - m);
        float s = e0 + e1;
#pragma unroll
        for (int o = 16; o; o >>= 1) s += __shfl_xor_sync(0xFFFFFFFFu, s, o);
        float p0 = e0 / s, p1 = e1 / s;

        unsigned long long v0 = ((unsigned long long)(__float_as_uint(p0) | 0x80000000u) << 32)
                              | (unsigned)(63 - lane);
        unsigned long long v1 = ((unsigned long long)(__float_as_uint(p1) | 0x80000000u) << 32)
                              | (unsigned)(31 - lane);
#pragma unroll
        for (int size = 2; size <= 64; size <<= 1) {
#pragma unroll
            for (int stride = size >> 1; stride > 0; stride >>= 1) {
                if (stride == 32) {
                    unsigned long long mx = v0 > v1 ? v0 : v1;
                    unsigned long long mn = v0 > v1 ? v1 : v0;
                    v0 = mx; v1 = mn;
                } else {
                    unsigned long long q0 = __shfl_xor_sync(0xFFFFFFFFu, v0, stride);
                    unsigned long long q1 = __shfl_xor_sync(0xFFFFFFFFu, v1, stride);
                    bool low  = ((lane & stride) == 0);
                    bool asc0 = ((lane & size) != 0);
                    bool asc1 = (((lane + 32) & size) != 0);
                    v0 = ((low == asc0) ? (v0 < q0) : (v0 > q0)) ? v0 : q0;
                    v1 = ((low == asc1) ? (v1 < q1) : (v1 > q1)) ? v1 : q1;
                }
            }
        }
        float a = __uint_as_float((unsigned)(v0 >> 32) & 0x7FFFFFFFu);
        float b = __uint_as_float((unsigned)(v1 >> 32) & 0x7FFFFFFFu);
        float ia = a, ib = b;
#pragma unroll
        for (int o = 1; o < 32; o <<= 1) {
            float t = __shfl_up_sync(0xFFFFFFFFu, ia, o);
            if (lane >= o) ia += t;
            float t2 = __shfl_up_sync(0xFFFFFFFFu, ib, o);
            if (lane >= o) ib += t2;
        }
        float totalA = __shfl_sync(0xFFFFFFFFu, ia, 31);
        float S0 = ia - a;
        float S1 = totalA + ib - b;
        unsigned key0 = (S0 < 0.9f) ? mono_key(a - (float)(lane + 1))  : 0u;
        unsigned key1 = (S1 < 0.9f) ? mono_key(b - (float)(lane + 33)) : 0u;
        int idx0 = 63 - (int)(v0 & 63u);
        int idx1 = 63 - (int)(v1 & 63u);

        unsigned* sk = (unsigned*)(sm_l + tL * 65);
        sk[idx0] = key0;
        sk[idx1] = key1;
        __syncwarp();
        unsigned k0 = sk[lane], k1 = sk[lane + 32];
        g_keys[(size_t)tok * E + lane]      = k0;
        g_keys[(size_t)tok * E + lane + 32] = k1;
        g_logits[(size_t)tok * E + lane]      = p0;
        g_logits[(size_t)tok * E + lane + 32] = p1;

        int etop1 = __shfl_sync(0xFFFFFFFFu, idx0, 0);
        int etop2 = __shfl_sync(0xFFFFFFFFu, idx0, 1);
        float ptop = __shfl_sync(0xFFFFFFFFu, a, 0);
        float t1a = __shfl_sync(0xFFFFFFFFu, l0, etop1 & 31);
        float t1b = __shfl_sync(0xFFFFFFFFu, l1, etop1 & 31);
        float t2a = __shfl_sync(0xFFFFFFFFu, l0, etop2 & 31);
        float t2b = __shfl_sync(0xFFFFFFFFu, l1, etop2 & 31);
        float lt1 = (etop1 < 32) ? t1a : t1b;
        float lt2 = (etop2 < 32) ? t2a : t2b;
        if (lane == 0) {
            out_top1[tok] = (float)etop1;
            atomicAdd(&g_fi[etop1], 1.f);
            atomicAdd(&g_pi[etop1], ptop);
            if ((lt1 - lt2) < 1e-4f) {
                int sp = atomicAdd(&g_nsus, 1);
                if (sp < MAXSUS)
                    g_sus[sp] = (unsigned)tok | ((unsigned)etop1 << 15) | ((unsigned)etop2 << 21);
            }
        }
    }
    __syncthreads();

    // ---- expert-major keyT tile: 64 experts x 128 tokens, coalesced 512B runs ----
    for (int i = tid; i < E * BM; i += 256) {
        int e = i >> 7, tl = i & 127;
        g_keyT[(size_t)e * N + n0 + tl] = ((unsigned*)(sm_l + tl * 65))[e];
    }
}

// ---------------- fp64 argmax repair: one BLOCK per suspect ----------------
__global__ __launch_bounds__(128) void repair_kernel(const float* __restrict__ x,
                                                     const float* __restrict__ w,
                                                     float* __restrict__ out_top1) {
    __shared__ double reda[4], redb[4];
    int n = g_nsus;
    if (n > MAXSUS) n = MAXSUS;
    int tid = threadIdx.x, lane = tid & 31, wrp = tid >> 5;
    for (int s = blockIdx.x; s < n; s += gridDim.x) {
        unsigned pk = g_sus[s];
        int t  = (int)(pk & 0x7FFFu);
        int ea = (int)((pk >> 15) & 63u);
        int eb = (int)((pk >> 21) & 63u);
        const float4* xr = (const float4*)(x + (size_t)t * H);
        const float4* wa = (const float4*)(w + (size_t)ea * H);
        const float4* wb = (const float4*)(w + (size_t)eb * H);
        int i0 = tid * 2;
        float4 x0 = xr[i0], x1 = xr[i0 + 1];
        float4 a0 = wa[i0], a1 = wa[i0 + 1];
        float4 b0 = wb[i0], b1 = wb[i0 + 1];
        double da = (double)x0.x * a0.x + (double)x0.y * a0.y
                  + (double)x0.z * a0.z + (double)x0.w * a0.w
                  + (double)x1.x * a1.x + (double)x1.y * a1.y
                  + (double)x1.z * a1.z + (double)x1.w * a1.w;
        double db = (double)x0.x * b0.x + (double)x0.y * b0.y
                  + (double)x0.z * b0.z + (double)x0.w * b0.w
                  + (double)x1.x * b1.x + (double)x1.y * b1.y
                  + (double)x1.z * b1.z + (double)x1.w * b1.w;
#pragma unroll
        for (int o = 16; o; o >>= 1) {
            da += __shfl_xor_sync(0xFFFFFFFFu, da, o);
            db += __shfl_xor_sync(0xFFFFFFFFu, db, o);
        }
        if (lane == 0) { reda[wrp] = da; redb[wrp] = db; }
        __syncthreads();
        if (tid == 0) {
            double A = reda[0] + reda[1] + reda[2] + reda[3];
            double B = redb[0] + redb[1] + redb[2] + redb[3];
            int win = (B > A || (B == A && eb < ea)) ? eb : ea;
            out_top1[t] = (float)win;
        }
        __syncthreads();
    }
}

// ---------------- select pass kernels: 3-pass 11/11/10-bit radix ----------------
__global__ __launch_bounds__(256) void hist_kernel(int N, int pass) {
    int e = blockIdx.x / SEG, seg = blockIdx.x % SEG;
    __shared__ unsigned h[2048];
    int tid = threadIdx.x;
    for (int i = tid; i < 2048; i += 256) h[i] = 0u;
    __syncthreads();
    unsigned pref = g_prefix[e];
    const uint4* col = (const uint4*)(g_keyT + (size_t)e * N + (size_t)seg * (N / SEG));
    int n4 = (N / SEG) >> 2;
    for (int i = tid; i < n4; i += 256) {
        uint4 kv = col[i];
        unsigned ks[4] = {kv.x, kv.y, kv.z, kv.w};
#pragma unroll
        for (int j = 0; j < 4; j++) {
            unsigned k = ks[j];
            if (!k) continue;
            bool mt; unsigned d;
            if (pass == 0)      { mt = true;                 d = k >> 21; }
            else if (pass == 1) { mt = ((k >> 21) == pref);  d = (k >> 10) & 0x7FFu; }
            else                { mt = ((k >> 10) == pref);  d = k & 0x3FFu; }
            if (mt) atomicAdd(&h[d], 1u);
        }
    }
    __syncthreads();
    for (int i = tid; i < 2048; i += 256) if (h[i]) atomicAdd(&g_hist[e][i], h[i]);
}

__global__ __launch_bounds__(256) void scan_kernel(int pass) {
    int e = blockIdx.x, t = threadIdx.x;
    __shared__ unsigned part[256], incl[256];
    __shared__ int found;
    if (t == 0) found = 0;
    unsigned mybin[8];
    unsigned s = 0;
#pragma unroll
    for (int j = 0; j < 8; j++) { mybin[j] = g_hist[e][2047 - (8 * t + j)]; s += mybin[j]; }
    part[t] = s; incl[t] = s;
    __syncthreads();
    for (int off = 1; off < 256; off <<= 1) {
        unsigned v = (t >= off) ? incl[t - off] : 0u;
        __syncthreads();
        incl[t] += v;
        __syncthreads();
    }
    unsigned rem = g_rem[e];
    unsigned ex = incl[t] - part[t];
    if (ex < rem && incl[t] >= rem) {
        unsigned r = rem - ex;
        int digit = 0;
#pragma unroll
        for (int j = 0; j < 8; j++) {
            unsigned cnt = mybin[j];
            if (cnt >= r) { digit = 2047 - (8 * t + j); break; }
            r -= cnt;
        }
        if (pass == 0)      g_prefix[e] = (unsigned)digit;
        else if (pass == 1) g_prefix[e] = (g_prefix[e] << 11) | (unsigned)digit;
        else                g_thresh[e] = (g_prefix[e] << 10) | (unsigned)digit;
        g_rem[e] = r;
        found = 1;
    }
    __syncthreads();
    if (!found && t == 0) {
        if (pass == 2) g_thresh[e] = 1u;   // keep every assigned token
        else g_rem[e] = 0xFFFFFFFFu;
    }
#pragma unroll
    for (int j = 0; j < 8; j++) g_hist[e][t * 8 + j] = 0u;
}

// ---------------- finalize mask + scores + aux ----------------
__global__ __launch_bounds__(256) void finalize_kernel(float* __restrict__ mask_out,
                                                       float* __restrict__ scores_out,
                                                       float* __restrict__ out_aux, int N) {
    __shared__ unsigned th[64];
    int t = threadIdx.x;
    if (blockIdx.x == 0 && t < 32) {
        float v = g_fi[t] * g_pi[t] + g_fi[t + 32] * g_pi[t + 32];
#pragma unroll
        for (int o = 16; o; o >>= 1) v += __shfl_xor_sync(0xFFFFFFFFu, v, o);
        if (t == 0) out_aux[0] = (float)E * (v / ((float)N * (float)N)) * 0.01f;
    }
    if (t < 64) th[t] = g_thresh[t];
    __syncthreads();
    size_t base = (size_t)blockIdx.x * 2048 + (size_t)t * 8;
#pragma unroll
    for (int j = 0; j < 2; j++) {
        size_t o = base + (size_t)j * 4;
        uint4  k = *(const uint4*)(g_keys + o);
        float4 p = *(const float4*)(g_logits + o);
        int e0 = (int)(o & 63);
        float4 mo, so;
        bool b0 = k.x && k.x >= th[e0 + 0];
        bool b1 = k.y && k.y >= th[e0 + 1];
        bool b2 = k.z && k.z >= th[e0 + 2];
        bool b3 = k.w && k.w >= th[e0 + 3];
        mo.x = b0 ? 1.f : 0.f; so.x = b0 ? p.x : 0.f;
        mo.y = b1 ? 1.f : 0.f; so.y = b1 ? p.y : 0.f;
        mo.z = b2 ? 1.f : 0.f; so.z = b2 ? p.z : 0.f;
        mo.w = b3 ? 1.f : 0.f; so.w = b3 ? p.w : 0.f;
        *(float4*)(mask_out + o)   = mo;
        *(float4*)(scores_out + o) = so;
    }
}

// ---------------- launch ----------------
extern "C" void kernel_launch(void* const* d_in, const int* in_sizes, int n_in,
                              void* d_out, int out_size) {
    const float* x = (const float*)d_in[0];
    const float* w = (const float*)d_in[1];
    int N = in_sizes[0] / H;            // 32768
    int C = (N + E - 1) / E;            // capacity (factor 1.0)
    if (C > N) C = N;

    float* out      = (float*)d_out;
    float* mask_out = out;
    float* scr_out  = out + (size_t)N * E;
    float* aux_out  = out + (size_t)2 * N * E;
    float* top1_out = out + (size_t)2 * N * E + 1;

    cudaFuncSetAttribute(gemm_router_kernel, cudaFuncAttributeMaxDynamicSharedMemorySize, SMEM_BYTES);

    convinit_kernel<<<(E * H + 255) / 256, 256>>>(w, C);
    gemm_router_kernel<<<N / BM, 256, SMEM_BYTES>>>(x, top1_out, N);
    repair_kernel<<<512, 128>>>(x, w, top1_out);
    for (int p = 0; p < 3; p++) {
        hist_kernel<<<E * SEG, 256>>>(N, p);
        scan_kernel<<<E, 256>>>(p);
    }
    finalize_kernel<<<(N * E) / 2048, 256>>>(mask_out, scr_out, aux_out, N);
}

// round 12
// speedup vs baseline: 1.1181x; 1.0818x over previous
#include <cuda_runtime.h>
#include <cuda_bf16.h>
#include <math.h>
#include <stdint.h>

#define H 1024
#define E 64
#define MAXN 32768
#define BM 128
#define AST 144u          // padded smem row stride for B (bytes)
#define MAXSUS 8192
#define SEG 8

// gemm smem: B only, double-buffered. stage = hi(9216) + lo(9216)
#define B_LO    9216u
#define B_STAGE 18432u
#define SMEM_BYTES 36864

// ---------------- scratch (no allocation allowed) ----------------
__device__ float         g_logits[(size_t)MAXN * E];
__device__ unsigned      g_keys[(size_t)MAXN * E];
__device__ unsigned      g_keyT[(size_t)E * MAXN];
__device__ unsigned      g_hist[E][2048];
__device__ unsigned      g_prefix[E];
__device__ unsigned      g_rem[E];
__device__ unsigned      g_thresh[E];
__device__ __align__(256) __nv_bfloat16 g_whi[E * H];
__device__ __align__(256) __nv_bfloat16 g_wlo[E * H];
__device__ float         g_fi[E];
__device__ float         g_pi[E];
__device__ int           g_nsus;
__device__ unsigned      g_sus[MAXSUS];

__device__ __forceinline__ unsigned mono_key(float f) {
    unsigned u = __float_as_uint(f);
    return (u & 0x80000000u) ? ~u : (u | 0x80000000u);
}

static __device__ __forceinline__ uint32_t smem_u32(const void* p) {
    uint32_t a;
    asm("{ .reg .u64 t; cvta.to.shared.u64 t, %1; cvt.u32.u64 %0, t; }" : "=r"(a) : "l"(p));
    return a;
}
static __device__ __forceinline__ void cp16(uint32_t dst, const void* src) {
    asm volatile("cp.async.ca.shared.global [%0], [%1], 16;" :: "r"(dst), "l"(src) : "memory");
}
static __device__ __forceinline__ void ldm_x4(uint32_t* r, uint32_t addr) {
    asm volatile("ldmatrix.sync.aligned.m8n8.x4.shared.b16 {%0,%1,%2,%3}, [%4];"
                 : "=r"(r[0]), "=r"(r[1]), "=r"(r[2]), "=r"(r[3]) : "r"(addr));
}
static __device__ __forceinline__ void mma16816(float* c, const uint32_t* a, const uint32_t* b) {
    asm volatile("mma.sync.aligned.m16n8k16.row.col.f32.bf16.bf16.f32 "
                 "{%0,%1,%2,%3}, {%4,%5,%6,%7}, {%8,%9}, {%0,%1,%2,%3};"
                 : "+f"(c[0]), "+f"(c[1]), "+f"(c[2]), "+f"(c[3])
                 : "r"(a[0]), "r"(a[1]), "r"(a[2]), "r"(a[3]), "r"(b[0]), "r"(b[1]));
}
static __device__ __forceinline__ void cvt_split(float a, float b, uint32_t& hi, uint32_t& lo) {
    __nv_bfloat162 h = __floats2bfloat162_rn(a, b);
    hi = *reinterpret_cast<uint32_t*>(&h);
    __nv_bfloat162 l = __floats2bfloat162_rn(a - __low2float(h), b - __high2float(h));
    lo = *reinterpret_cast<uint32_t*>(&l);
}

// ---------------- convert gate_w + init (fused) ----------------
__global__ __launch_bounds__(256) void convinit_kernel(const float* __restrict__ w, int C) {
    int i = blockIdx.x * blockDim.x + threadIdx.x;
    if (i < E * H) {
        float v = w[i];
        __nv_bfloat16 h = __float2bfloat16(v);
        g_whi[i] = h;
        g_wlo[i] = __float2bfloat16(v - __bfloat162float(h));
    }
    if (blockIdx.x == 0 && threadIdx.x < E) {
        int t = threadIdx.x;
        g_fi[t] = 0.f; g_pi[t] = 0.f;
        g_prefix[t] = 0u; g_rem[t] = (unsigned)C;
        if (t == 0) g_nsus = 0;
    }
}

// ---------------- HMMA GEMM: A in registers (fragment-direct), B dbl-buffered smem ----------------
__global__ __launch_bounds__(256, 2) void gemm_mma_kernel(const float* __restrict__ x) {
    extern __shared__ __align__(16) char smem[];
    uint32_t sb = smem_u32(smem);
    int tid = threadIdx.x, lane = tid & 31, wid = tid >> 5;
    int n0 = blockIdx.x * BM;
    int m0 = wid * 16;

    const float* xA  = x + (size_t)(n0 + m0 + (lane >> 2)) * H + (lane & 3) * 2;
    const float* xA8 = xA + 8 * H;

    uint32_t b_ld_off = (uint32_t)((lane & 7) + ((lane >> 4) & 1) * 8) * AST
                      + (uint32_t)((lane >> 3) & 1) * 16u;

    float acc[8][4];
#pragma unroll
    for (int i = 0; i < 8; i++)
#pragma unroll
        for (int j = 0; j < 4; j++) acc[i][j] = 0.f;

    float2 cur[16], nxt[16];
#pragma unroll
    for (int kt = 0; kt < 4; kt++) {
        int kb = kt * 16;
        cur[kt * 4 + 0] = *(const float2*)(xA  + kb);
        cur[kt * 4 + 1] = *(const float2*)(xA8 + kb);
        cur[kt * 4 + 2] = *(const float2*)(xA  + kb + 8);
        cur[kt * 4 + 3] = *(const float2*)(xA8 + kb + 8);
    }
#pragma unroll
    for (int j = 0; j < 2; j++) {
        int idx = tid * 2 + j;
        int n = idx >> 3, seg = idx & 7;
        uint32_t off = (uint32_t)n * AST + (uint32_t)seg * 16u;
        cp16(sb + off,        (const char*)g_whi + n * 2048 + seg * 16);
        cp16(sb + B_LO + off, (const char*)g_wlo + n * 2048 + seg * 16);
    }
    asm volatile("cp.async.commit_group;" ::: "memory");
    asm volatile("cp.async.wait_group 0;" ::: "memory");
    __syncthreads();

    for (int c = 0; c < 16; c++) {
        int cs = c & 1, ns = cs ^ 1;
        if (c < 15) {
            uint32_t bb = sb + (uint32_t)ns * B_STAGE;
#pragma unroll
            for (int j = 0; j < 2; j++) {
                int idx = tid * 2 + j;
                int n = idx >> 3, seg = idx & 7;
                uint32_t off = (uint32_t)n * AST + (uint32_t)seg * 16u;
                cp16(bb + off,        (const char*)g_whi + n * 2048 + (c + 1) * 128 + seg * 16);
                cp16(bb + B_LO + off, (const char*)g_wlo + n * 2048 + (c + 1) * 128 + seg * 16);
            }
            asm volatile("cp.async.commit_group;" ::: "memory");
            int cb = (c + 1) * 64;
#pragma unroll
            for (int kt = 0; kt < 4; kt++) {
                int kb = cb + kt * 16;
                nxt[kt * 4 + 0] = *(const float2*)(xA  + kb);
                nxt[kt * 4 + 1] = *(const float2*)(xA8 + kb);
                nxt[kt * 4 + 2] = *(const float2*)(xA  + kb + 8);
                nxt[kt * 4 + 3] = *(const float2*)(xA8 + kb + 8);
            }
        }
        uint32_t bbase = sb + (uint32_t)cs * B_STAGE;
#pragma unroll
        for (int kt = 0; kt < 4; kt++) {
            uint32_t ko = (uint32_t)kt * 32u;
            uint32_t ah[4], al[4];
#pragma unroll
            for (int j = 0; j < 4; j++)
                cvt_split(cur[kt * 4 + j].x, cur[kt * 4 + j].y, ah[j], al[j]);
#pragma unroll
            for (int np = 0; np < 4; np++) {
                uint32_t noff = (uint32_t)np * 16u * AST;
                uint32_t bh[4], bl[4];
                ldm_x4(bh, bbase + b_ld_off + noff + ko);
                ldm_x4(bl, bbase + B_LO + b_ld_off + noff + ko);
                mma16816(acc[2 * np],     ah, bh);
                mma16816(acc[2 * np + 1], ah, bh + 2);
                mma16816(acc[2 * np],     ah, bl);
                mma16816(acc[2 * np + 1], ah, bl + 2);
                mma16816(acc[2 * np],     al, bh);
                mma16816(acc[2 * np + 1], al, bh + 2);
            }
        }
        if (c < 15) asm volatile("cp.async.wait_group 0;" ::: "memory");
        __syncthreads();
#pragma unroll
        for (int i = 0; i < 16; i++) cur[i] = nxt[i];
    }

    int tok = n0 + m0 + (lane >> 2);
    int ec = 2 * (lane & 3);
#pragma unroll
    for (int nt = 0; nt < 8; nt++) {
        *(float2*)(g_logits + (size_t)tok * E + nt * 8 + ec)       = make_float2(acc[nt][0], acc[nt][1]);
        *(float2*)(g_logits + (size_t)(tok + 8) * E + nt * 8 + ec) = make_float2(acc[nt][2], acc[nt][3]);
    }
}

// ---------------- router: softmax + bitonic-sort rank/threshold (1 warp / token) ----------------
__global__ __launch_bounds__(256) void router_kernel(float* __restrict__ out_top1, int N) {
    __shared__ unsigned skey[8][64];
    int warp = threadIdx.x >> 5, lane = threadIdx.x & 31;
    int tok0 = blockIdx.x * 8;
    int tok  = tok0 + warp;

    float* row = g_logits + (size_t)tok * E;
    float l0 = row[lane], l1 = row[lane + 32];
    float m = fmaxf(l0, l1);
#pragma unroll
    for (int o = 16; o; o >>= 1) m = fmaxf(m, __shfl_xor_sync(0xFFFFFFFFu, m, o));
    float e0 = expf(l0 - m), e1 = expf(l1 - m);
    float s = e0 + e1;
#pragma unroll
    for (int o = 16; o; o >>= 1) s += __shfl_xor_sync(0xFFFFFFFFu, s, o);
    float p0 = e0 / s, p1 = e1 / s;

    unsigned long long v0 = ((unsigned long long)(__float_as_uint(p0) | 0x80000000u) << 32)
                          | (unsigned)(63 - lane);
    unsigned long long v1 = ((unsigned long long)(__float_as_uint(p1) | 0x80000000u) << 32)
                          | (unsigned)(31 - lane);

#pragma unroll
    for (int size = 2; size <= 64; size <<= 1) {
#pragma unroll
        for (int stride = size >> 1; stride > 0; stride >>= 1) {
            if (stride == 32) {
                unsigned long long mx = v0 > v1 ? v0 : v1;
                unsigned long long mn = v0 > v1 ? v1 : v0;
                v0 = mx; v1 = mn;
            } else {
                unsigned long long q0 = __shfl_xor_sync(0xFFFFFFFFu, v0, stride);
                unsigned long long q1 = __shfl_xor_sync(0xFFFFFFFFu, v1, stride);
                bool low  = ((lane & stride) == 0);
                bool asc0 = ((lane & size) != 0);
                bool asc1 = (((lane + 32) & size) != 0);
                v0 = ((low == asc0) ? (v0 < q0) : (v0 > q0)) ? v0 : q0;
                v1 = ((low == asc1) ? (v1 < q1) : (v1 > q1)) ? v1 : q1;
            }
        }
    }

    float a = __uint_as_float((unsigned)(v0 >> 32) & 0x7FFFFFFFu);
    float b = __uint_as_float((unsigned)(v1 >> 32) & 0x7FFFFFFFu);
    float ia = a, ib = b;
#pragma unroll
    for (int o = 1; o < 32; o <<= 1) {
        float t = __shfl_up_sync(0xFFFFFFFFu, ia, o);
        if (lane >= o) ia += t;
        float t2 = __shfl_up_sync(0xFFFFFFFFu, ib, o);
        if (lane >= o) ib += t2;
    }
    float totalA = __shfl_sync(0xFFFFFFFFu, ia, 31);
    float S0 = ia - a;
    float S1 = totalA + ib - b;
    unsigned key0 = (S0 < 0.9f) ? mono_key(a - (float)(lane + 1))  : 0u;
    unsigned key1 = (S1 < 0.9f) ? mono_key(b - (float)(lane + 33)) : 0u;
    int idx0 = 63 - (int)(v0 & 63u);
    int idx1 = 63 - (int)(v1 & 63u);
    skey[warp][idx0] = key0;
    skey[warp][idx1] = key1;
    __syncwarp();
    unsigned k0 = skey[warp][lane], k1 = skey[warp][lane + 32];
    g_keys[(size_t)tok * E + lane]      = k0;
    g_keys[(size_t)tok * E + lane + 32] = k1;
    row[lane]      = p0;
    row[lane + 32] = p1;

    int etop1 = __shfl_sync(0xFFFFFFFFu, idx0, 0);
    int etop2 = __shfl_sync(0xFFFFFFFFu, idx0, 1);
    float ptop = __shfl_sync(0xFFFFFFFFu, a, 0);
    if (lane == 0) {
        out_top1[tok] = (float)etop1;
        atomicAdd(&g_fi[etop1], 1.f);
        atomicAdd(&g_pi[etop1], ptop);
    }
    float t1a = __shfl_sync(0xFFFFFFFFu, l0, etop1 & 31);
    float t1b = __shfl_sync(0xFFFFFFFFu, l1, etop1 & 31);
    float t2a = __shfl_sync(0xFFFFFFFFu, l0, etop2 & 31);
    float t2b = __shfl_sync(0xFFFFFFFFu, l1, etop2 & 31);
    float lt1 = (etop1 < 32) ? t1a : t1b;
    float lt2 = (etop2 < 32) ? t2a : t2b;
    if (lane == 0 && (lt1 - lt2) < 1e-4f) {
        int sp = atomicAdd(&g_nsus, 1);
        if (sp < MAXSUS)
            g_sus[sp] = (unsigned)tok | ((unsigned)etop1 << 15) | ((unsigned)etop2 << 21);
    }

    __syncthreads();
    for (int i = threadIdx.x; i < 512; i += 256) {
        int e = i >> 3, c = i & 7;
        g_keyT[(size_t)e * N + tok0 + c] = skey[c][e];
    }
}

// ---------------- fp64 argmax repair: one BLOCK per suspect, float4 loads ----------------
__global__ __launch_bounds__(128) void repair_kernel(const float* __restrict__ x,
                                                     const float* __restrict__ w,
                                                     float* __restrict__ out_top1) {
    __shared__ double reda[4], redb[4];
    int n = g_nsus;
    if (n > MAXSUS) n = MAXSUS;
    int tid = threadIdx.x, lane = tid & 31, wrp = tid >> 5;
    for (int s = blockIdx.x; s < n; s += gridDim.x) {
        unsigned pk = g_sus[s];
        int t  = (int)(pk & 0x7FFFu);
        int ea = (int)((pk >> 15) & 63u);
        int eb = (int)((pk >> 21) & 63u);
        const float4* xr = (const float4*)(x + (size_t)t * H);
        const float4* wa = (const float4*)(w + (size_t)ea * H);
        const float4* wb = (const float4*)(w + (size_t)eb * H);
        int i0 = tid * 2;
        float4 x0 = xr[i0], x1 = xr[i0 + 1];
        float4 a0 = wa[i0], a1 = wa[i0 + 1];
        float4 b0 = wb[i0], b1 = wb[i0 + 1];
        double da = (double)x0.x * a0.x + (double)x0.y * a0.y
                  + (double)x0.z * a0.z + (double)x0.w * a0.w
                  + (double)x1.x * a1.x + (double)x1.y * a1.y
                  + (double)x1.z * a1.z + (double)x1.w * a1.w;
        double db = (double)x0.x * b0.x + (double)x0.y * b0.y
                  + (double)x0.z * b0.z + (double)x0.w * b0.w
                  + (double)x1.x * b1.x + (double)x1.y * b1.y
                  + (double)x1.z * b1.z + (double)x1.w * b1.w;
#pragma unroll
        for (int o = 16; o; o >>= 1) {
            da += __shfl_xor_sync(0xFFFFFFFFu, da, o);
            db += __shfl_xor_sync(0xFFFFFFFFu, db, o);
        }
        if (lane == 0) { reda[wrp] = da; redb[wrp] = db; }
        __syncthreads();
        if (tid == 0) {
            double A = reda[0] + reda[1] + reda[2] + reda[3];
            double B = redb[0] + redb[1] + redb[2] + redb[3];
            int win = (B > A || (B == A && eb < ea)) ? eb : ea;
            out_top1[t] = (float)win;
        }
        __syncthreads();
    }
}

// ---------------- select pass kernels: 3-pass 11/11/10-bit radix, MLP-4 loads ----------------
__global__ __launch_bounds__(256) void hist_kernel(int N, int pass) {
    int e = blockIdx.x >> 3, seg = blockIdx.x & 7;   // SEG = 8
    __shared__ unsigned h[2048];
    int tid = threadIdx.x;
    for (int i = tid; i < 2048; i += 256) h[i] = 0u;
    __syncthreads();
    unsigned pref = g_prefix[e];
    const uint4* col = (const uint4*)(g_keyT + (size_t)e * N + (size_t)seg * (N >> 3));
    // (N/8)/4 = 1024 uint4 per block -> 4 per thread, all loads issued before atomics
    uint4 kv[4];
#pragma unroll
    for (int j = 0; j < 4; j++) kv[j] = col[tid + j * 256];
#pragma unroll
    for (int j = 0; j < 4; j++) {
        unsigned ks[4] = {kv[j].x, kv[j].y, kv[j].z, kv[j].w};
#pragma unroll
        for (int q = 0; q < 4; q++) {
            unsigned k = ks[q];
            if (!k) continue;
            bool mt; unsigned d;
            if (pass == 0)      { mt = true;                 d = k >> 21; }
            else if (pass == 1) { mt = ((k >> 21) == pref);  d = (k >> 10) & 0x7FFu; }
            else                { mt = ((k >> 10) == pref);  d = k & 0x3FFu; }
            if (mt) atomicAdd(&h[d], 1u);
        }
    }
    __syncthreads();
    for (int i = tid; i < 2048; i += 256) if (h[i]) atomicAdd(&g_hist[e][i], h[i]);
}

__global__ __launch_bounds__(256) void scan_kernel(int pass) {
    int e = blockIdx.x, t = threadIdx.x;
    __shared__ unsigned part[256], incl[256];
    __shared__ int found;
    if (t == 0) found = 0;
    unsigned mybin[8];
    unsigned s = 0;
#pragma unroll
    for (int j = 0; j < 8; j++) { mybin[j] = g_hist[e][2047 - (8 * t + j)]; s += mybin[j]; }
    part[t] = s; incl[t] = s;
    __syncthreads();
    for (int off = 1; off < 256; off <<= 1) {
        unsigned v = (t >= off) ? incl[t - off] : 0u;
        __syncthreads();
        incl[t] += v;
        __syncthreads();
    }
    unsigned rem = g_rem[e];
    unsigned ex = incl[t] - part[t];
    if (ex < rem && incl[t] >= rem) {
        unsigned r = rem - ex;
        int digit = 0;
#pragma unroll
        for (int j = 0; j < 8; j++) {
            unsigned cnt = mybin[j];
            if (cnt >= r) { digit = 2047 - (8 * t + j); break; }
            r -= cnt;
        }
        if (pass == 0)      g_prefix[e] = (unsigned)digit;
        else if (pass == 1) g_prefix[e] = (g_prefix[e] << 11) | (unsigned)digit;
        else                g_thresh[e] = (g_prefix[e] << 10) | (unsigned)digit;
        g_rem[e] = r;
        found = 1;
    }
    __syncthreads();
    if (!found && t == 0) {
        if (pass == 2) g_thresh[e] = 1u;   // keep every assigned token
        else g_rem[e] = 0xFFFFFFFFu;
    }
#pragma unroll
    for (int j = 0; j < 8; j++) g_hist[e][t * 8 + j] = 0u;
}

// ---------------- finalize mask + scores + aux ----------------
__global__ __launch_bounds__(256) void finalize_kernel(float* __restrict__ mask_out,
                                                       float* __restrict__ scores_out,
                                                       float* __restrict__ out_aux, int N) {
    __shared__ unsigned th[64];
    int t = threadIdx.x;
    if (blockIdx.x == 0 && t < 32) {
        float v = g_fi[t] * g_pi[t] + g_fi[t + 32] * g_pi[t + 32];
#pragma unroll
        for (int o = 16; o; o >>= 1) v += __shfl_xor_sync(0xFFFFFFFFu, v, o);
        if (t == 0) out_aux[0] = (float)E * (v / ((float)N * (float)N)) * 0.01f;
    }
    if (t < 64) th[t] = g_thresh[t];
    __syncthreads();
    size_t base = (size_t)blockIdx.x * 2048 + (size_t)t * 8;
#pragma unroll
    for (int j = 0; j < 2; j++) {
        size_t o = base + (size_t)j * 4;
        uint4  k = *(const uint4*)(g_keys + o);
        float4 p = *(const float4*)(g_logits + o);
        int e0 = (int)(o & 63);
        float4 mo, so;
        bool b0 = k.x && k.x >= th[e0 + 0];
        bool b1 = k.y && k.y >= th[e0 + 1];
        bool b2 = k.z && k.z >= th[e0 + 2];
        bool b3 = k.w && k.w >= th[e0 + 3];
        mo.x = b0 ? 1.f : 0.f; so.x = b0 ? p.x : 0.f;
        mo.y = b1 ? 1.f : 0.f; so.y = b1 ? p.y : 0.f;
        mo.z = b2 ? 1.f : 0.f; so.z = b2 ? p.z : 0.f;
        mo.w = b3 ? 1.f : 0.f; so.w = b3 ? p.w : 0.f;
        *(float4*)(mask_out + o)   = mo;
        *(float4*)(scores_out + o) = so;
    }
}

// ---------------- launch ----------------
extern "C" void kernel_launch(void* const* d_in, const int* in_sizes, int n_in,
                              void* d_out, int out_size) {
    const float* x = (const float*)d_in[0];
    const float* w = (const float*)d_in[1];
    int N = in_sizes[0] / H;            // 32768
    int C = (N + E - 1) / E;            // capacity (factor 1.0)
    if (C > N) C = N;

    float* out      = (float*)d_out;
    float* mask_out = out;
    float* scr_out  = out + (size_t)N * E;
    float* aux_out  = out + (size_t)2 * N * E;
    float* top1_out = out + (size_t)2 * N * E + 1;

    cudaFuncSetAttribute(gemm_mma_kernel, cudaFuncAttributeMaxDynamicSharedMemorySize, SMEM_BYTES);

    convinit_kernel<<<(E * H + 255) / 256, 256>>>(w, C);
    gemm_mma_kernel<<<N / BM, 256, SMEM_BYTES>>>(x);
    router_kernel<<<N / 8, 256>>>(top1_out, N);
    repair_kernel<<<512, 128>>>(x, w, top1_out);
    for (int p = 0; p < 3; p++) {
        hist_kernel<<<E * SEG, 256>>>(N, p);
        scan_kernel<<<E, 256>>>(p);
    }
    finalize_kernel<<<(N * E) / 2048, 256>>>(mask_out, scr_out, aux_out, N);
}